// round 9
// baseline (speedup 1.0000x reference)
#include <cuda_runtime.h>
#include <cstdint>

#define B_TOT   4096
#define NTOK    49
#define CDIM    128
#define NHEAD   4
#define HDIM    32
#define TPB     512
#define SCALE   0.17677669529663687f   /* 32^-0.5 */
#define FULLM   0xffffffffu
#define NEG_INF (__int_as_float(0xff800000))

typedef unsigned long long u64;

// ---- packed f32x2 helpers (sm_100+ PTX) --------------------------------
static __device__ __forceinline__ void ffma2(u64& acc, u64 a, u64 b) {
    asm("fma.rn.f32x2 %0, %1, %2, %0;" : "+l"(acc) : "l"(a), "l"(b));
}
static __device__ __forceinline__ float2 unpackf2(u64 v) {
    float2 r;
    asm("mov.b64 {%0, %1}, %2;" : "=f"(r.x), "=f"(r.y) : "l"(v));
    return r;
}

// ---- shared memory layout ----------------------------------------------
// wsp: W chunk packed by k-quads: ulonglong2 wsp[k4][col], row pad 129
// xp : x (then gated attn output) packed by k-quads: xp[k4][n], row pad 51
// qp/ktp: q,k packed by d-PAIRS: u64 (v[n][2d],v[n][2d+1]) at [d2*51 + n]
// vp : v packed by m-PAIRS: u64 (v[2m2][c],v[2m2+1][c]) at [m2*130 + c]
// pp : per-warp prob rows: pp[wy*364 + r*52 + m]  (m pad 49..51 zeroed)
struct Smem {
    ulonglong2 wsp[32 * 129];              // 66.0 KB
    ulonglong2 xp[32 * 51];                // 26.1 KB
    u64  qp[64 * 51];                      // 26.1 KB
    u64  ktp[64 * 51];                     // 26.1 KB
    u64  vp[25 * 130];                     // 26.0 KB
    float pp[16 * 7 * 52];                 // 23.3 KB
    int   ridx[NTOK * NTOK];               //  9.6 KB
    float rtab[169 * 4];
    float bqs[3 * CDIM];
    float pbs[CDIM];
    float invT[64];
    float uBs[64];
    float gts[NHEAD * NTOK];
};
#define SMEM_BYTES ((int)sizeof(Smem))

// stage a 128x128 weight block W[c][k] -> packed layout; LDG.128 + STS.128
static __device__ __forceinline__ void stage_w(Smem* sm, const float* __restrict__ src, int tid) {
    float* wf = reinterpret_cast<float*>(sm->wsp);
    const float4* s4 = reinterpret_cast<const float4*>(src);
    #pragma unroll
    for (int i = 0; i < 8; i++) {
        int idx = tid + i * TPB;          // idx = c*32 + kq
        int c  = idx >> 5;
        int kq = idx & 31;
        float4 v = s4[idx];
        *reinterpret_cast<float4*>(wf + kq * 516 + c * 4) = v;
    }
}

// NR rows x 64 cols GEMM (col-half cg): acc[rr][cc] packed (lo=even k, hi=odd k)
template <int NR>
static __device__ __forceinline__ void gemm_block(const Smem* sm, int n0, int cg,
                                                  int lane, u64 (&acc)[7][2]) {
    #pragma unroll
    for (int rr = 0; rr < NR; rr++) { acc[rr][0] = 0ull; acc[rr][1] = 0ull; }

    const ulonglong2* wq = sm->wsp;
    const ulonglong2* xq = sm->xp;
    const int wbase = cg * 64 + lane;
    #pragma unroll 4
    for (int k4 = 0; k4 < 32; k4++) {
        ulonglong2 w0 = wq[k4 * 129 + wbase];
        ulonglong2 w1 = wq[k4 * 129 + wbase + 32];
        ulonglong2 xv[NR];
        #pragma unroll
        for (int rr = 0; rr < NR; rr++) xv[rr] = xq[k4 * 51 + n0 + rr];  // broadcast
        #pragma unroll
        for (int rr = 0; rr < NR; rr++) {
            ffma2(acc[rr][0], xv[rr].x, w0.x);
            ffma2(acc[rr][1], xv[rr].x, w1.x);
        }
        #pragma unroll
        for (int rr = 0; rr < NR; rr++) {
            ffma2(acc[rr][0], xv[rr].y, w0.y);
            ffma2(acc[rr][1], xv[rr].y, w1.y);
        }
    }
}

// attention for one (head, row-group) block; R rows, lanes = keys (QK) / dims (PV)
template <int R>
static __device__ __forceinline__ void attn_block(Smem* sm, float* xpf,
                                                  int h, int n0, int lane, int wy) {
    const int h16 = h * 16;        // d2 base for this head
    const int hd0 = h * HDIM;      // channel base
    const u64* ktu = sm->ktp;
    const u64* qpu = sm->qp;
    const u64* vpu = sm->vp;
    float* ppw = sm->pp + wy * 364;

    // ---- QK: packed over d-pairs, broadcast q ----
    u64 s0[R], s1[R];
    #pragma unroll
    for (int r = 0; r < R; r++) { s0[r] = 0ull; s1[r] = 0ull; }
    #pragma unroll 8
    for (int dd = 0; dd < 16; dd++) {
        u64 k0 = ktu[(h16 + dd) * 51 + lane];
        u64 k1 = ktu[(h16 + dd) * 51 + 32 + lane];   // lanes>=17: dead (guarded below)
        #pragma unroll
        for (int r = 0; r < R; r++) {
            u64 qv = qpu[(h16 + dd) * 51 + n0 + r];  // 8B broadcast
            ffma2(s0[r], qv, k0);
            ffma2(s1[r], qv, k1);
        }
    }

    // ---- softmax (lanes = keys) ----
    float uB0 = sm->uBs[lane];
    float uB1 = (lane < 17) ? sm->uBs[lane + 32] : 0.f;
    #pragma unroll
    for (int r = 0; r < R; r++) {
        int n = n0 + r;
        float2 t0 = unpackf2(s0[r]);
        float2 t1 = unpackf2(s1[r]);
        float sc0 = t0.x + t0.y;
        float sc1 = t1.x + t1.y;
        float bias0 = sm->rtab[sm->ridx[n * NTOK + lane] * 4 + h] - uB0;
        float a0 = fmaf(sc0, SCALE, bias0);
        float a1 = NEG_INF;
        if (lane < 17) {
            float bias1 = sm->rtab[sm->ridx[n * NTOK + lane + 32] * 4 + h] - uB1;
            a1 = fmaf(sc1, SCALE, bias1);
        }
        float mx = fmaxf(a0, a1);
        #pragma unroll
        for (int o = 16; o > 0; o >>= 1) mx = fmaxf(mx, __shfl_xor_sync(FULLM, mx, o));
        float e0 = __expf(a0 - mx);
        float e1 = (lane < 17) ? __expf(a1 - mx) : 0.f;
        float smv = e0 + e1;
        #pragma unroll
        for (int o = 16; o > 0; o >>= 1) smv += __shfl_xor_sync(FULLM, smv, o);
        float inv = __fdividef(1.f, smv);
        ppw[r * 52 + lane] = e0 * inv;
        if (lane < 17) ppw[r * 52 + 32 + lane] = e1 * inv;
    }
    __syncwarp();

    // ---- PV: packed over m-pairs, broadcast probs; lanes = head dims ----
    const u64* ppu = reinterpret_cast<const u64*>(ppw);  // [r*26 + m2]
    u64 o2[R];
    #pragma unroll
    for (int r = 0; r < R; r++) o2[r] = 0ull;
    #pragma unroll 5
    for (int m2 = 0; m2 < 25; m2++) {
        u64 vv = vpu[m2 * 130 + hd0 + lane];
        #pragma unroll
        for (int r = 0; r < R; r++) {
            u64 pv = ppu[r * 26 + m2];               // 8B broadcast
            ffma2(o2[r], pv, vv);
        }
    }

    // gated write into packed xp layout (input to proj GEMM); conflict-free
    const int c = hd0 + lane;
    const int cbase = (c >> 2) * 204 + (c & 3);
    #pragma unroll
    for (int r = 0; r < R; r++) {
        int n = n0 + r;
        float2 t = unpackf2(o2[r]);
        xpf[cbase + n * 4] = (t.x + t.y) * sm->gts[h * NTOK + n];
    }
    __syncwarp();   // pp reads done before next block overwrites
}

__global__ void __launch_bounds__(TPB, 1)
attn_win_kernel(const float* __restrict__ x,
                const float* __restrict__ ut,
                const float* __restrict__ ub,
                const float* __restrict__ gate,
                const float* __restrict__ qkv_w,
                const float* __restrict__ qkv_b,
                const float* __restrict__ proj_w,
                const float* __restrict__ proj_b,
                const float* __restrict__ rel_table,
                const int*   __restrict__ rel_index,
                float* __restrict__ out) {
    extern __shared__ char smem_raw[];
    Smem* sm = reinterpret_cast<Smem*>(smem_raw);
    float* xpf  = reinterpret_cast<float*>(sm->xp);
    float* qpf  = reinterpret_cast<float*>(sm->qp);
    float* ktpf = reinterpret_cast<float*>(sm->ktp);
    float* vpf  = reinterpret_cast<float*>(sm->vp);

    const int b    = blockIdx.x;
    const int tid  = threadIdx.x;
    const int lane = tid & 31;
    const int wy   = tid >> 5;

    // ---------------- stage constants + x + zero pads ----------------
    for (int i = tid; i < NTOK * NTOK; i += TPB) sm->ridx[i] = rel_index[i];
    for (int i = tid; i < 169 * 4; i += TPB)     sm->rtab[i] = rel_table[i];
    for (int i = tid; i < 3 * CDIM; i += TPB)    sm->bqs[i]  = qkv_b[i];
    if (tid < CDIM) sm->pbs[tid] = proj_b[tid];
    // zero pp (covers prob pads m=49..51)
    for (int i = tid; i < 16 * 7 * 52; i += TPB) sm->pp[i] = 0.f;
    // zero ktp pads (m = 49,50 of every d2 row)
    if (tid < 256) {
        int d2 = tid >> 2, off = tid & 3;
        ktpf[d2 * 102 + 98 + off] = 0.f;
    }
    // zero vp pad row m=49 (hi half of m2=24)
    if (tid < 128) vpf[24 * 260 + 2 * tid + 1] = 0.f;
    if (tid < NTOK) {
        float t  = ut[b * NTOK + tid];
        float sg = 1.f / (1.f + __expf(-t));
        sm->invT[tid] = 1.f / (0.1f + 4.f * sg);
        float u = ub[b * NTOK + tid];
        sm->uBs[tid] = u > 0.f ? u : 0.f;
    }
    if (tid < NHEAD * NTOK) sm->gts[tid] = gate[(size_t)b * (NHEAD * NTOK) + tid];
    {   // x: float4 per (n, k-quad): LDG.128 + STS.128, packed layout
        const float4* x4 = reinterpret_cast<const float4*>(x + (size_t)b * (NTOK * CDIM));
        #pragma unroll
        for (int i = 0; i < 4; i++) {
            int idx = tid + i * TPB;       // idx = n*32 + kq
            if (idx < NTOK * 32) {
                int n = idx >> 5, kq = idx & 31;
                float4 v = x4[idx];
                *reinterpret_cast<float4*>(xpf + kq * 204 + n * 4) = v;
            }
        }
    }
    stage_w(sm, qkv_w, tid);   // chunk 0 (q)
    __syncthreads();

    // warp partition: 8 row-groups x 2 col-halves
    const int rg = wy >> 1, cg = wy & 1;
    const int n0 = (rg == 0) ? 0 : 6 * rg + 1;
    const int NRv = (rg == 0) ? 7 : 6;

    // ---------------- qkv GEMM (q, k, v chunks) ----------------------
    u64 acc[7][2];
    for (int j = 0; j < 3; j++) {
        if (rg == 0) gemm_block<7>(sm, n0, cg, lane, acc);
        else         gemm_block<6>(sm, n0, cg, lane, acc);
        #pragma unroll
        for (int rr = 0; rr < 7; rr++) {
            if (rr < NRv) {
                int n = n0 + rr;
                #pragma unroll
                for (int cc = 0; cc < 2; cc++) {
                    int c = cg * 64 + 32 * cc + lane;
                    float2 s = unpackf2(acc[rr][cc]);
                    float v = s.x + s.y + sm->bqs[j * CDIM + c];
                    if (j == 0)      qpf[(c >> 1) * 102 + n * 2 + (c & 1)] = v * sm->invT[n];
                    else if (j == 1) ktpf[(c >> 1) * 102 + n * 2 + (c & 1)] = v;
                    else             vpf[(n >> 1) * 260 + (c << 1) + (n & 1)] = v;
                }
            }
        }
        __syncthreads();
        if (j < 2) { stage_w(sm, qkv_w + (j + 1) * 128 * 128, tid); __syncthreads(); }
    }
    // wsp free during attention: stage proj_w now
    stage_w(sm, proj_w, tid);

    // ---------------- attention: 32 blocks = 4 heads x 8 row-groups --
    #pragma unroll
    for (int it = 0; it < 2; it++) {
        int bk = wy + 16 * it;
        int h = bk >> 3, g = bk & 7;
        if (g == 0) attn_block<7>(sm, xpf, h, 0, lane, wy);
        else        attn_block<6>(sm, xpf, h, 6 * g + 1, lane, wy);
    }
    __syncthreads();   // proj_w staged + all xp writes visible

    // ---------------- output projection ------------------------------
    if (rg == 0) gemm_block<7>(sm, n0, cg, lane, acc);
    else         gemm_block<6>(sm, n0, cg, lane, acc);
    #pragma unroll
    for (int rr = 0; rr < 7; rr++) {
        if (rr < NRv) {
            int n = n0 + rr;
            #pragma unroll
            for (int cc = 0; cc < 2; cc++) {
                int c = cg * 64 + 32 * cc + lane;
                float2 s = unpackf2(acc[rr][cc]);
                out[(size_t)b * (NTOK * CDIM) + n * CDIM + c] = s.x + s.y + sm->pbs[c];
            }
        }
    }
}

extern "C" void kernel_launch(void* const* d_in, const int* in_sizes, int n_in,
                              void* d_out, int out_size) {
    const float* x      = (const float*)d_in[0];
    const float* ut     = (const float*)d_in[1];
    const float* ubias  = (const float*)d_in[2];
    const float* gate   = (const float*)d_in[3];
    const float* qkv_w  = (const float*)d_in[4];
    const float* qkv_b  = (const float*)d_in[5];
    const float* proj_w = (const float*)d_in[6];
    const float* proj_b = (const float*)d_in[7];
    const float* rtab   = (const float*)d_in[8];
    const int*   ridx   = (const int*)d_in[9];
    float* out = (float*)d_out;

    cudaFuncSetAttribute(attn_win_kernel,
                         cudaFuncAttributeMaxDynamicSharedMemorySize, SMEM_BYTES);
    attn_win_kernel<<<B_TOT, TPB, SMEM_BYTES>>>(
        x, ut, ubias, gate, qkv_w, qkv_b, proj_w, proj_b, rtab, ridx, out);
}